// round 1
// baseline (speedup 1.0000x reference)
#include <cuda_runtime.h>
#include <cstddef>

#define B_ 8
#define N_ 4096
#define S_ 4096
#define D_ 1024
#define H_ 16
#define A_ 8
#define DH 64
#define NA 512          // N_/A_
#define KKEEP 2048
#define SCALE_ 0.125f   // (D/H)^-0.5 = 64^-0.5

// ------------------------- scratch (device globals) -------------------------
__device__ float g_kc[(size_t)B_ * S_ * D_];
__device__ float g_vc[(size_t)B_ * S_ * D_];
__device__ float g_qo[(size_t)B_ * N_ * D_];
__device__ float g_outpre[(size_t)B_ * N_ * D_];
__device__ float g_attn_agent[(size_t)B_ * H_ * A_ * S_];
__device__ float g_agent_raw[B_ * A_ * D_];
__device__ float g_agent_tok[B_ * A_ * D_];
__device__ float g_qa[B_ * A_ * D_];
__device__ float g_ka[B_ * A_ * D_];
__device__ float g_va[B_ * A_ * D_];
__device__ float g_agent_out[B_ * A_ * D_];

// ------------------------- agent token mean ---------------------------------
// agent_raw[b][a][d] = mean over 512 tokens of query[b][a*512+n][d]
__global__ void mean_kernel(const float* __restrict__ q) {
    int idx = blockIdx.x * blockDim.x + threadIdx.x;   // over B*A*D
    int d = idx & (D_ - 1);
    int ba = idx / D_;
    int a = ba & (A_ - 1);
    int b = ba / A_;
    const float* base = q + ((size_t)(b * N_ + a * NA)) * D_ + d;
    float s = 0.f;
#pragma unroll 8
    for (int n = 0; n < NA; n++) s += base[(size_t)n * D_];
    g_agent_raw[idx] = s * (1.0f / NA);
}

// ------------------------- generic SGEMM: C = A(MxK) @ W(KxK') + bias -------
// K = K' = 1024 fixed. Tile 128x128x16, 256 threads, 8x8 per thread.
__global__ __launch_bounds__(256) void sgemm_bias(
    const float* __restrict__ A, const float* __restrict__ W,
    const float* __restrict__ bias, float* __restrict__ C, int M) {
    __shared__ float As[16][128];
    __shared__ float Bs[16][128];

    const int t = threadIdx.x;
    const int row0 = blockIdx.y * 128;
    const int col0 = blockIdx.x * 128;
    const int tr = t >> 4;        // 0..15
    const int tc = t & 15;        // 0..15

    float acc[8][8];
#pragma unroll
    for (int i = 0; i < 8; i++)
#pragma unroll
        for (int j = 0; j < 8; j++) acc[i][j] = 0.f;

    for (int k0 = 0; k0 < 1024; k0 += 16) {
        // load A tile (128 rows x 16 cols): 512 float4, 2 per thread
#pragma unroll
        for (int l = 0; l < 2; l++) {
            int i = t * 2 + l;
            int r = i >> 2;          // row in tile
            int c4 = i & 3;          // float4 within row
            float4 v = make_float4(0.f, 0.f, 0.f, 0.f);
            if (row0 + r < M)
                v = *(const float4*)&A[(size_t)(row0 + r) * 1024 + k0 + c4 * 4];
            As[c4 * 4 + 0][r] = v.x;
            As[c4 * 4 + 1][r] = v.y;
            As[c4 * 4 + 2][r] = v.z;
            As[c4 * 4 + 3][r] = v.w;
        }
        // load W tile (16 rows x 128 cols): 512 float4, 2 per thread
#pragma unroll
        for (int l = 0; l < 2; l++) {
            int i = t * 2 + l;
            int r = i >> 5;          // 0..15
            int c4 = i & 31;         // 0..31
            float4 v = *(const float4*)&W[(size_t)(k0 + r) * 1024 + col0 + c4 * 4];
            *(float4*)&Bs[r][c4 * 4] = v;
        }
        __syncthreads();
#pragma unroll
        for (int k = 0; k < 16; k++) {
            float ra[8], rb[8];
#pragma unroll
            for (int i = 0; i < 8; i++) ra[i] = As[k][tr * 8 + i];
#pragma unroll
            for (int j = 0; j < 8; j++) rb[j] = Bs[k][tc * 8 + j];
#pragma unroll
            for (int i = 0; i < 8; i++)
#pragma unroll
                for (int j = 0; j < 8; j++) acc[i][j] += ra[i] * rb[j];
        }
        __syncthreads();
    }

    float bv[8];
#pragma unroll
    for (int j = 0; j < 8; j++) bv[j] = bias[col0 + tc * 8 + j];

#pragma unroll
    for (int i = 0; i < 8; i++) {
        int r = row0 + tr * 8 + i;
        if (r < M) {
            float4 o0 = make_float4(acc[i][0] + bv[0], acc[i][1] + bv[1],
                                    acc[i][2] + bv[2], acc[i][3] + bv[3]);
            float4 o1 = make_float4(acc[i][4] + bv[4], acc[i][5] + bv[5],
                                    acc[i][6] + bv[6], acc[i][7] + bv[7]);
            *(float4*)&C[(size_t)r * 1024 + col0 + tc * 8 + 0] = o0;
            *(float4*)&C[(size_t)r * 1024 + col0 + tc * 8 + 4] = o1;
        }
    }
}

// ------------------------- agent scores: q_a . k_c ---------------------------
// attn_agent[b][h][a][s] = SCALE * sum_d qa[b,a,h*64+d] * kc[b,s,h*64+d]
__global__ __launch_bounds__(256) void agent_scores_kernel() {
    int bh = blockIdx.x;
    int b = bh / H_, h = bh % H_;
    int t = threadIdx.x;
    int s = blockIdx.y * 256 + t;
    __shared__ float qs[A_][DH];
    for (int i = t; i < A_ * DH; i += 256) {
        int a = i / DH, d = i % DH;
        qs[a][d] = g_qa[(b * A_ + a) * D_ + h * DH + d];
    }
    __syncthreads();
    const float4* krow = (const float4*)&g_kc[((size_t)b * S_ + s) * D_ + h * DH];
    float acc[A_];
#pragma unroll
    for (int a = 0; a < A_; a++) acc[a] = 0.f;
#pragma unroll
    for (int d4 = 0; d4 < DH / 4; d4++) {
        float4 kv = krow[d4];
#pragma unroll
        for (int a = 0; a < A_; a++) {
            acc[a] += kv.x * qs[a][d4 * 4 + 0] + kv.y * qs[a][d4 * 4 + 1] +
                      kv.z * qs[a][d4 * 4 + 2] + kv.w * qs[a][d4 * 4 + 3];
        }
    }
#pragma unroll
    for (int a = 0; a < A_; a++)
        g_attn_agent[(((size_t)bh) * A_ + a) * S_ + s] = acc[a] * SCALE_;
}

// ------------------------- exact top-k threshold + softmax -------------------
// One block per (b,h,a) row: bitonic-sort a copy of the 4096 scores in smem,
// thresh = 2048th largest = sorted_ascending[2048]; keep x >= thresh (matches
// jnp.where(attn < thresh, -inf)); masked softmax; write attn_agent_w.
__global__ __launch_bounds__(512) void topk_softmax_kernel(float* __restrict__ w_out) {
    __shared__ float v[S_];
    __shared__ float srt[S_];
    __shared__ float red[512];
    int row = blockIdx.x;
    int t = threadIdx.x;
    const float* src = g_attn_agent + (size_t)row * S_;
    for (int i = t; i < S_; i += 512) {
        float x = src[i];
        v[i] = x;
        srt[i] = x;
    }
    __syncthreads();
    for (int k = 2; k <= S_; k <<= 1) {
        for (int j = k >> 1; j > 0; j >>= 1) {
            for (int i = t; i < S_; i += 512) {
                int ixj = i ^ j;
                if (ixj > i) {
                    bool up = ((i & k) == 0);
                    float a = srt[i], b = srt[ixj];
                    if ((a > b) == up) { srt[i] = b; srt[ixj] = a; }
                }
            }
            __syncthreads();
        }
    }
    float thresh = srt[S_ - KKEEP];
    float mx = srt[S_ - 1];
    float lsum = 0.f;
    for (int i = t; i < S_; i += 512) {
        float x = v[i];
        float e = (x >= thresh) ? expf(x - mx) : 0.f;
        v[i] = e;
        lsum += e;
    }
    red[t] = lsum;
    __syncthreads();
    for (int o = 256; o > 0; o >>= 1) {
        if (t < o) red[t] += red[t + o];
        __syncthreads();
    }
    float inv = 1.f / red[0];
    float* dst = w_out + (size_t)row * S_;
    for (int i = t; i < S_; i += 512) dst[i] = v[i] * inv;
}

// ------------------------- agent_out = w @ v_c -------------------------------
// agent_out[b][a][h*64+d] = sum_s w[b,h,a,s] * vc[b,s,h*64+d]
__global__ __launch_bounds__(512) void agent_out_kernel(const float* __restrict__ w) {
    int bh = blockIdx.x;
    int b = bh / H_, h = bh % H_;
    int t = threadIdx.x;
    int a = t / DH, d = t % DH;
    __shared__ float ws[A_][256];
    const float* wbase = w + ((size_t)bh * A_) * S_;
    const float* vbase = g_vc + ((size_t)b * S_) * D_ + h * DH;
    float acc = 0.f;
    for (int s0 = 0; s0 < S_; s0 += 256) {
        for (int i = t; i < A_ * 256; i += 512) {
            int aa = i >> 8, ss = i & 255;
            ws[aa][ss] = wbase[(size_t)aa * S_ + s0 + ss];
        }
        __syncthreads();
#pragma unroll 8
        for (int ss = 0; ss < 256; ss++)
            acc += ws[a][ss] * vbase[(size_t)(s0 + ss) * D_ + d];
        __syncthreads();
    }
    g_agent_out[(b * A_ + a) * D_ + h * DH + d] = acc;
}

// ------------------------- fused final attention -----------------------------
// scores[n][a] = SCALE * q_o[b,n,h].k_a[b,a,h]; softmax over a (A=8);
// write attn_final; outpre[b,n,h*64+d] = sum_a w[a]*v_a[b,a,h*64+d]
__global__ __launch_bounds__(256) void final_attn_kernel(float* __restrict__ attn_out) {
    int bh = blockIdx.x;
    int b = bh / H_, h = bh % H_;
    int t = threadIdx.x;
    int n = blockIdx.y * 256 + t;
    __shared__ float ks[A_][DH], vs[A_][DH];
    for (int i = t; i < A_ * DH; i += 256) {
        int a = i / DH, d = i % DH;
        ks[a][d] = g_ka[(b * A_ + a) * D_ + h * DH + d];
        vs[a][d] = g_va[(b * A_ + a) * D_ + h * DH + d];
    }
    __syncthreads();
    const float4* qrow = (const float4*)&g_qo[((size_t)b * N_ + n) * D_ + h * DH];
    float sc[A_];
#pragma unroll
    for (int a = 0; a < A_; a++) sc[a] = 0.f;
#pragma unroll
    for (int d4 = 0; d4 < DH / 4; d4++) {
        float4 q = qrow[d4];
#pragma unroll
        for (int a = 0; a < A_; a++) {
            sc[a] += q.x * ks[a][d4 * 4 + 0] + q.y * ks[a][d4 * 4 + 1] +
                     q.z * ks[a][d4 * 4 + 2] + q.w * ks[a][d4 * 4 + 3];
        }
    }
    float mx = -1e30f;
#pragma unroll
    for (int a = 0; a < A_; a++) {
        sc[a] *= SCALE_;
        mx = fmaxf(mx, sc[a]);
    }
    float sum = 0.f;
#pragma unroll
    for (int a = 0; a < A_; a++) {
        sc[a] = expf(sc[a] - mx);
        sum += sc[a];
    }
    float inv = 1.f / sum;
#pragma unroll
    for (int a = 0; a < A_; a++) sc[a] *= inv;

    // attn_final (B,H,N,A)
    float* ao = attn_out + (((size_t)bh) * N_ + n) * A_;
#pragma unroll
    for (int a = 0; a < A_; a++) ao[a] = sc[a];

    float4* orow = (float4*)&g_outpre[((size_t)b * N_ + n) * D_ + h * DH];
#pragma unroll
    for (int d4 = 0; d4 < DH / 4; d4++) {
        float4 o = make_float4(0.f, 0.f, 0.f, 0.f);
#pragma unroll
        for (int a = 0; a < A_; a++) {
            float w = sc[a];
            o.x += w * vs[a][d4 * 4 + 0];
            o.y += w * vs[a][d4 * 4 + 1];
            o.z += w * vs[a][d4 * 4 + 2];
            o.w += w * vs[a][d4 * 4 + 3];
        }
        orow[d4] = o;
    }
}

// ------------------------- launch ------------------------------------------
extern "C" void kernel_launch(void* const* d_in, const int* in_sizes, int n_in,
                              void* d_out, int out_size) {
    const float* query = (const float*)d_in[0];
    const float* key = (const float*)d_in[1];
    const float* value = (const float*)d_in[2];
    const float* W_agent = (const float*)d_in[3];
    const float* b_agent = (const float*)d_in[4];
    const float* W_qa = (const float*)d_in[5];
    const float* b_qa = (const float*)d_in[6];
    const float* W_kc = (const float*)d_in[7];
    const float* b_kc = (const float*)d_in[8];
    const float* W_vc = (const float*)d_in[9];
    const float* b_vc = (const float*)d_in[10];
    const float* W_qo = (const float*)d_in[11];
    const float* b_qo = (const float*)d_in[12];
    const float* W_ka = (const float*)d_in[13];
    const float* b_ka = (const float*)d_in[14];
    const float* W_va = (const float*)d_in[15];
    const float* b_va = (const float*)d_in[16];
    const float* W_proj = (const float*)d_in[17];
    const float* b_proj = (const float*)d_in[18];

    float* out0 = (float*)d_out;                                   // (B,N,D)
    float* out_attn_final = out0 + (size_t)B_ * N_ * D_;           // (B,H,N,A)
    float* out_attn_agent_w = out_attn_final + (size_t)B_ * H_ * N_ * A_; // (B,H,A,S)

    float *p_raw, *p_tok, *p_qa, *p_kc, *p_vc, *p_qo, *p_ka, *p_va, *p_aout, *p_outpre;
    cudaGetSymbolAddress((void**)&p_raw, g_agent_raw);
    cudaGetSymbolAddress((void**)&p_tok, g_agent_tok);
    cudaGetSymbolAddress((void**)&p_qa, g_qa);
    cudaGetSymbolAddress((void**)&p_kc, g_kc);
    cudaGetSymbolAddress((void**)&p_vc, g_vc);
    cudaGetSymbolAddress((void**)&p_qo, g_qo);
    cudaGetSymbolAddress((void**)&p_ka, g_ka);
    cudaGetSymbolAddress((void**)&p_va, g_va);
    cudaGetSymbolAddress((void**)&p_aout, g_agent_out);
    cudaGetSymbolAddress((void**)&p_outpre, g_outpre);

    const int MBIG = B_ * N_;   // 32768
    const int MSM = B_ * A_;    // 64
    dim3 gemm_big(8, MBIG / 128);
    dim3 gemm_small(8, 1);

    // 1. agent token mean
    mean_kernel<<<(B_ * A_ * D_) / 256, 256>>>(query);
    // 2. agent_tokens = mean @ W_agent + b
    sgemm_bias<<<gemm_small, 256>>>(p_raw, W_agent, b_agent, p_tok, MSM);
    // 3. q_a
    sgemm_bias<<<gemm_small, 256>>>(p_tok, W_qa, b_qa, p_qa, MSM);
    // 4-6. big projections
    sgemm_bias<<<gemm_big, 256>>>(key, W_kc, b_kc, p_kc, MBIG);
    sgemm_bias<<<gemm_big, 256>>>(value, W_vc, b_vc, p_vc, MBIG);
    sgemm_bias<<<gemm_big, 256>>>(query, W_qo, b_qo, p_qo, MBIG);
    // 7. agent scores
    agent_scores_kernel<<<dim3(B_ * H_, S_ / 256), 256>>>();
    // 8. top-k threshold + masked softmax -> attn_agent_w output region
    topk_softmax_kernel<<<B_ * H_ * A_, 512>>>(out_attn_agent_w);
    // 9. agent_out = w @ v_c
    agent_out_kernel<<<B_ * H_, 512>>>(out_attn_agent_w);
    // 10-11. k_a, v_a
    sgemm_bias<<<gemm_small, 256>>>(p_aout, W_ka, b_ka, p_ka, MSM);
    sgemm_bias<<<gemm_small, 256>>>(p_aout, W_va, b_va, p_va, MSM);
    // 12. final attention (writes attn_final output + outpre)
    final_attn_kernel<<<dim3(B_ * H_, N_ / 256), 256>>>(out_attn_final);
    // 13. out = outpre @ W_proj + b_proj
    sgemm_bias<<<gemm_big, 256>>>(p_outpre, W_proj, b_proj, out0, MBIG);
}

// round 2
// speedup vs baseline: 1.0002x; 1.0002x over previous
#include <cuda_runtime.h>
#include <cstddef>

#define B_ 8
#define N_ 4096
#define S_ 4096
#define D_ 1024
#define H_ 16
#define A_ 8
#define DH 64
#define NA 512          // N_/A_
#define KKEEP 2048
#define SCALE_ 0.125f   // (D/H)^-0.5 = 64^-0.5

// ------------------------- scratch (device globals) -------------------------
__device__ float g_kc[(size_t)B_ * S_ * D_];
__device__ float g_vc[(size_t)B_ * S_ * D_];
__device__ float g_qo[(size_t)B_ * N_ * D_];
__device__ float g_outpre[(size_t)B_ * N_ * D_];
__device__ float g_attn_agent[(size_t)B_ * H_ * A_ * S_];
__device__ float g_agent_raw[B_ * A_ * D_];
__device__ float g_agent_tok[B_ * A_ * D_];
__device__ float g_qa[B_ * A_ * D_];
__device__ float g_ka[B_ * A_ * D_];
__device__ float g_va[B_ * A_ * D_];
__device__ float g_agent_out[B_ * A_ * D_];

// ------------------------- agent token mean ---------------------------------
// agent_raw[b][a][d] = mean over 512 tokens of query[b][a*512+n][d]
__global__ void mean_kernel(const float* __restrict__ q) {
    int idx = blockIdx.x * blockDim.x + threadIdx.x;   // over B*A*D
    int d = idx & (D_ - 1);
    int ba = idx / D_;
    int a = ba & (A_ - 1);
    int b = ba / A_;
    const float* base = q + ((size_t)(b * N_ + a * NA)) * D_ + d;
    float s = 0.f;
#pragma unroll 8
    for (int n = 0; n < NA; n++) s += base[(size_t)n * D_];
    g_agent_raw[idx] = s * (1.0f / NA);
}

// ------------------------- generic SGEMM: C = A(MxK) @ W(KxK') + bias -------
// K = K' = 1024 fixed. Tile 128x128x16, 256 threads, 8x8 per thread.
__global__ __launch_bounds__(256) void sgemm_bias(
    const float* __restrict__ A, const float* __restrict__ W,
    const float* __restrict__ bias, float* __restrict__ C, int M) {
    __shared__ float As[16][128];
    __shared__ float Bs[16][128];

    const int t = threadIdx.x;
    const int row0 = blockIdx.y * 128;
    const int col0 = blockIdx.x * 128;
    const int tr = t >> 4;        // 0..15
    const int tc = t & 15;        // 0..15

    float acc[8][8];
#pragma unroll
    for (int i = 0; i < 8; i++)
#pragma unroll
        for (int j = 0; j < 8; j++) acc[i][j] = 0.f;

    for (int k0 = 0; k0 < 1024; k0 += 16) {
        // load A tile (128 rows x 16 cols): 512 float4, 2 per thread
#pragma unroll
        for (int l = 0; l < 2; l++) {
            int i = t * 2 + l;
            int r = i >> 2;          // row in tile
            int c4 = i & 3;          // float4 within row
            float4 v = make_float4(0.f, 0.f, 0.f, 0.f);
            if (row0 + r < M)
                v = *(const float4*)&A[(size_t)(row0 + r) * 1024 + k0 + c4 * 4];
            As[c4 * 4 + 0][r] = v.x;
            As[c4 * 4 + 1][r] = v.y;
            As[c4 * 4 + 2][r] = v.z;
            As[c4 * 4 + 3][r] = v.w;
        }
        // load W tile (16 rows x 128 cols): 512 float4, 2 per thread
#pragma unroll
        for (int l = 0; l < 2; l++) {
            int i = t * 2 + l;
            int r = i >> 5;          // 0..15
            int c4 = i & 31;         // 0..31
            float4 v = *(const float4*)&W[(size_t)(k0 + r) * 1024 + col0 + c4 * 4];
            *(float4*)&Bs[r][c4 * 4] = v;
        }
        __syncthreads();
#pragma unroll
        for (int k = 0; k < 16; k++) {
            float ra[8], rb[8];
#pragma unroll
            for (int i = 0; i < 8; i++) ra[i] = As[k][tr * 8 + i];
#pragma unroll
            for (int j = 0; j < 8; j++) rb[j] = Bs[k][tc * 8 + j];
#pragma unroll
            for (int i = 0; i < 8; i++)
#pragma unroll
                for (int j = 0; j < 8; j++) acc[i][j] += ra[i] * rb[j];
        }
        __syncthreads();
    }

    float bv[8];
#pragma unroll
    for (int j = 0; j < 8; j++) bv[j] = bias[col0 + tc * 8 + j];

#pragma unroll
    for (int i = 0; i < 8; i++) {
        int r = row0 + tr * 8 + i;
        if (r < M) {
            float4 o0 = make_float4(acc[i][0] + bv[0], acc[i][1] + bv[1],
                                    acc[i][2] + bv[2], acc[i][3] + bv[3]);
            float4 o1 = make_float4(acc[i][4] + bv[4], acc[i][5] + bv[5],
                                    acc[i][6] + bv[6], acc[i][7] + bv[7]);
            *(float4*)&C[(size_t)r * 1024 + col0 + tc * 8 + 0] = o0;
            *(float4*)&C[(size_t)r * 1024 + col0 + tc * 8 + 4] = o1;
        }
    }
}

// ------------------------- agent scores: q_a . k_c ---------------------------
// attn_agent[b][h][a][s] = SCALE * sum_d qa[b,a,h*64+d] * kc[b,s,h*64+d]
__global__ __launch_bounds__(256) void agent_scores_kernel() {
    int bh = blockIdx.x;
    int b = bh / H_, h = bh % H_;
    int t = threadIdx.x;
    int s = blockIdx.y * 256 + t;
    __shared__ float qs[A_][DH];
    for (int i = t; i < A_ * DH; i += 256) {
        int a = i / DH, d = i % DH;
        qs[a][d] = g_qa[(b * A_ + a) * D_ + h * DH + d];
    }
    __syncthreads();
    const float4* krow = (const float4*)&g_kc[((size_t)b * S_ + s) * D_ + h * DH];
    float acc[A_];
#pragma unroll
    for (int a = 0; a < A_; a++) acc[a] = 0.f;
#pragma unroll
    for (int d4 = 0; d4 < DH / 4; d4++) {
        float4 kv = krow[d4];
#pragma unroll
        for (int a = 0; a < A_; a++) {
            acc[a] += kv.x * qs[a][d4 * 4 + 0] + kv.y * qs[a][d4 * 4 + 1] +
                      kv.z * qs[a][d4 * 4 + 2] + kv.w * qs[a][d4 * 4 + 3];
        }
    }
#pragma unroll
    for (int a = 0; a < A_; a++)
        g_attn_agent[(((size_t)bh) * A_ + a) * S_ + s] = acc[a] * SCALE_;
}

// ------------------------- exact top-k threshold + softmax -------------------
// One block per (b,h,a) row: bitonic-sort a copy of the 4096 scores in smem,
// thresh = 2048th largest = sorted_ascending[2048]; keep x >= thresh (matches
// jnp.where(attn < thresh, -inf)); masked softmax; write attn_agent_w.
__global__ __launch_bounds__(512) void topk_softmax_kernel(float* __restrict__ w_out) {
    __shared__ float v[S_];
    __shared__ float srt[S_];
    __shared__ float red[512];
    int row = blockIdx.x;
    int t = threadIdx.x;
    const float* src = g_attn_agent + (size_t)row * S_;
    for (int i = t; i < S_; i += 512) {
        float x = src[i];
        v[i] = x;
        srt[i] = x;
    }
    __syncthreads();
    for (int k = 2; k <= S_; k <<= 1) {
        for (int j = k >> 1; j > 0; j >>= 1) {
            for (int i = t; i < S_; i += 512) {
                int ixj = i ^ j;
                if (ixj > i) {
                    bool up = ((i & k) == 0);
                    float a = srt[i], b = srt[ixj];
                    if ((a > b) == up) { srt[i] = b; srt[ixj] = a; }
                }
            }
            __syncthreads();
        }
    }
    float thresh = srt[S_ - KKEEP];
    float mx = srt[S_ - 1];
    float lsum = 0.f;
    for (int i = t; i < S_; i += 512) {
        float x = v[i];
        float e = (x >= thresh) ? expf(x - mx) : 0.f;
        v[i] = e;
        lsum += e;
    }
    red[t] = lsum;
    __syncthreads();
    for (int o = 256; o > 0; o >>= 1) {
        if (t < o) red[t] += red[t + o];
        __syncthreads();
    }
    float inv = 1.f / red[0];
    float* dst = w_out + (size_t)row * S_;
    for (int i = t; i < S_; i += 512) dst[i] = v[i] * inv;
}

// ------------------------- agent_out = w @ v_c -------------------------------
// agent_out[b][a][h*64+d] = sum_s w[b,h,a,s] * vc[b,s,h*64+d]
__global__ __launch_bounds__(512) void agent_out_kernel(const float* __restrict__ w) {
    int bh = blockIdx.x;
    int b = bh / H_, h = bh % H_;
    int t = threadIdx.x;
    int a = t / DH, d = t % DH;
    __shared__ float ws[A_][256];
    const float* wbase = w + ((size_t)bh * A_) * S_;
    const float* vbase = g_vc + ((size_t)b * S_) * D_ + h * DH;
    float acc = 0.f;
    for (int s0 = 0; s0 < S_; s0 += 256) {
        for (int i = t; i < A_ * 256; i += 512) {
            int aa = i >> 8, ss = i & 255;
            ws[aa][ss] = wbase[(size_t)aa * S_ + s0 + ss];
        }
        __syncthreads();
#pragma unroll 8
        for (int ss = 0; ss < 256; ss++)
            acc += ws[a][ss] * vbase[(size_t)(s0 + ss) * D_ + d];
        __syncthreads();
    }
    g_agent_out[(b * A_ + a) * D_ + h * DH + d] = acc;
}

// ------------------------- fused final attention -----------------------------
// scores[n][a] = SCALE * q_o[b,n,h].k_a[b,a,h]; softmax over a (A=8);
// write attn_final; outpre[b,n,h*64+d] = sum_a w[a]*v_a[b,a,h*64+d]
__global__ __launch_bounds__(256) void final_attn_kernel(float* __restrict__ attn_out) {
    int bh = blockIdx.x;
    int b = bh / H_, h = bh % H_;
    int t = threadIdx.x;
    int n = blockIdx.y * 256 + t;
    __shared__ float ks[A_][DH], vs[A_][DH];
    for (int i = t; i < A_ * DH; i += 256) {
        int a = i / DH, d = i % DH;
        ks[a][d] = g_ka[(b * A_ + a) * D_ + h * DH + d];
        vs[a][d] = g_va[(b * A_ + a) * D_ + h * DH + d];
    }
    __syncthreads();
    const float4* qrow = (const float4*)&g_qo[((size_t)b * N_ + n) * D_ + h * DH];
    float sc[A_];
#pragma unroll
    for (int a = 0; a < A_; a++) sc[a] = 0.f;
#pragma unroll
    for (int d4 = 0; d4 < DH / 4; d4++) {
        float4 q = qrow[d4];
#pragma unroll
        for (int a = 0; a < A_; a++) {
            sc[a] += q.x * ks[a][d4 * 4 + 0] + q.y * ks[a][d4 * 4 + 1] +
                     q.z * ks[a][d4 * 4 + 2] + q.w * ks[a][d4 * 4 + 3];
        }
    }
    float mx = -1e30f;
#pragma unroll
    for (int a = 0; a < A_; a++) {
        sc[a] *= SCALE_;
        mx = fmaxf(mx, sc[a]);
    }
    float sum = 0.f;
#pragma unroll
    for (int a = 0; a < A_; a++) {
        sc[a] = expf(sc[a] - mx);
        sum += sc[a];
    }
    float inv = 1.f / sum;
#pragma unroll
    for (int a = 0; a < A_; a++) sc[a] *= inv;

    // attn_final (B,H,N,A)
    float* ao = attn_out + (((size_t)bh) * N_ + n) * A_;
#pragma unroll
    for (int a = 0; a < A_; a++) ao[a] = sc[a];

    float4* orow = (float4*)&g_outpre[((size_t)b * N_ + n) * D_ + h * DH];
#pragma unroll
    for (int d4 = 0; d4 < DH / 4; d4++) {
        float4 o = make_float4(0.f, 0.f, 0.f, 0.f);
#pragma unroll
        for (int a = 0; a < A_; a++) {
            float w = sc[a];
            o.x += w * vs[a][d4 * 4 + 0];
            o.y += w * vs[a][d4 * 4 + 1];
            o.z += w * vs[a][d4 * 4 + 2];
            o.w += w * vs[a][d4 * 4 + 3];
        }
        orow[d4] = o;
    }
}

// ------------------------- launch ------------------------------------------
extern "C" void kernel_launch(void* const* d_in, const int* in_sizes, int n_in,
                              void* d_out, int out_size) {
    const float* query = (const float*)d_in[0];
    const float* key = (const float*)d_in[1];
    const float* value = (const float*)d_in[2];
    const float* W_agent = (const float*)d_in[3];
    const float* b_agent = (const float*)d_in[4];
    const float* W_qa = (const float*)d_in[5];
    const float* b_qa = (const float*)d_in[6];
    const float* W_kc = (const float*)d_in[7];
    const float* b_kc = (const float*)d_in[8];
    const float* W_vc = (const float*)d_in[9];
    const float* b_vc = (const float*)d_in[10];
    const float* W_qo = (const float*)d_in[11];
    const float* b_qo = (const float*)d_in[12];
    const float* W_ka = (const float*)d_in[13];
    const float* b_ka = (const float*)d_in[14];
    const float* W_va = (const float*)d_in[15];
    const float* b_va = (const float*)d_in[16];
    const float* W_proj = (const float*)d_in[17];
    const float* b_proj = (const float*)d_in[18];

    float* out0 = (float*)d_out;                                   // (B,N,D)
    float* out_attn_final = out0 + (size_t)B_ * N_ * D_;           // (B,H,N,A)
    float* out_attn_agent_w = out_attn_final + (size_t)B_ * H_ * N_ * A_; // (B,H,A,S)

    float *p_raw, *p_tok, *p_qa, *p_kc, *p_vc, *p_qo, *p_ka, *p_va, *p_aout, *p_outpre;
    cudaGetSymbolAddress((void**)&p_raw, g_agent_raw);
    cudaGetSymbolAddress((void**)&p_tok, g_agent_tok);
    cudaGetSymbolAddress((void**)&p_qa, g_qa);
    cudaGetSymbolAddress((void**)&p_kc, g_kc);
    cudaGetSymbolAddress((void**)&p_vc, g_vc);
    cudaGetSymbolAddress((void**)&p_qo, g_qo);
    cudaGetSymbolAddress((void**)&p_ka, g_ka);
    cudaGetSymbolAddress((void**)&p_va, g_va);
    cudaGetSymbolAddress((void**)&p_aout, g_agent_out);
    cudaGetSymbolAddress((void**)&p_outpre, g_outpre);

    const int MBIG = B_ * N_;   // 32768
    const int MSM = B_ * A_;    // 64
    dim3 gemm_big(8, MBIG / 128);
    dim3 gemm_small(8, 1);

    // 1. agent token mean
    mean_kernel<<<(B_ * A_ * D_) / 256, 256>>>(query);
    // 2. agent_tokens = mean @ W_agent + b
    sgemm_bias<<<gemm_small, 256>>>(p_raw, W_agent, b_agent, p_tok, MSM);
    // 3. q_a
    sgemm_bias<<<gemm_small, 256>>>(p_tok, W_qa, b_qa, p_qa, MSM);
    // 4-6. big projections
    sgemm_bias<<<gemm_big, 256>>>(key, W_kc, b_kc, p_kc, MBIG);
    sgemm_bias<<<gemm_big, 256>>>(value, W_vc, b_vc, p_vc, MBIG);
    sgemm_bias<<<gemm_big, 256>>>(query, W_qo, b_qo, p_qo, MBIG);
    // 7. agent scores
    agent_scores_kernel<<<dim3(B_ * H_, S_ / 256), 256>>>();
    // 8. top-k threshold + masked softmax -> attn_agent_w output region
    topk_softmax_kernel<<<B_ * H_ * A_, 512>>>(out_attn_agent_w);
    // 9. agent_out = w @ v_c
    agent_out_kernel<<<B_ * H_, 512>>>(out_attn_agent_w);
    // 10-11. k_a, v_a
    sgemm_bias<<<gemm_small, 256>>>(p_aout, W_ka, b_ka, p_ka, MSM);
    sgemm_bias<<<gemm_small, 256>>>(p_aout, W_va, b_va, p_va, MSM);
    // 12. final attention (writes attn_final output + outpre)
    final_attn_kernel<<<dim3(B_ * H_, N_ / 256), 256>>>(out_attn_final);
    // 13. out = outpre @ W_proj + b_proj
    sgemm_bias<<<gemm_big, 256>>>(p_outpre, W_proj, b_proj, out0, MBIG);
}

// round 6
// speedup vs baseline: 1.1945x; 1.1942x over previous
#include <cuda_runtime.h>
#include <cstddef>
#include <cstdint>

#define B_ 8
#define N_ 4096
#define S_ 4096
#define D_ 1024
#define H_ 16
#define A_ 8
#define DH 64
#define NA 512
#define KKEEP 2048
#define SCALE_ 0.125f

// mma tiling
#define BM 128
#define BN 128
#define BK 32
#define PITCH 36                        // floats per smem row (144B, 16B-aligned)
#define ARR (128 * PITCH)               // 4608 floats per array
#define STAGEF (4 * ARR)                // Ah, Al, Bh, Bl
#define SMEM_MMA (2 * STAGEF * 4)       // bytes = 147456

__device__ float g_kc[(size_t)B_ * S_ * D_];
__device__ float g_vc[(size_t)B_ * S_ * D_];
__device__ float g_qo[(size_t)B_ * N_ * D_];
__device__ float g_outpre[(size_t)B_ * N_ * D_];
__device__ float g_attn_agent[(size_t)B_ * H_ * A_ * S_];
__device__ float g_agent_raw[B_ * A_ * D_];
__device__ float g_agent_tok[B_ * A_ * D_];
__device__ float g_qa[B_ * A_ * D_];
__device__ float g_ka[B_ * A_ * D_];
__device__ float g_va[B_ * A_ * D_];
__device__ float g_agent_out[B_ * A_ * D_];
__device__ float g_ah[(size_t)B_ * N_ * D_];
__device__ float g_al[(size_t)B_ * N_ * D_];
__device__ float g_bh[(size_t)D_ * D_];
__device__ float g_bl[(size_t)D_ * D_];

__device__ __forceinline__ uint32_t smem_u32(const void* p) {
    uint32_t a;
    asm("{ .reg .u64 t; cvta.to.shared.u64 t, %1; cvt.u32.u64 %0, t; }" : "=r"(a) : "l"(p));
    return a;
}
#define CP_ASYNC16(dst, src) \
    asm volatile("cp.async.cg.shared.global [%0], [%1], 16;" :: "r"(dst), "l"(src) : "memory")
#define CP_COMMIT() asm volatile("cp.async.commit_group;" ::: "memory")
#define CP_WAIT1() asm volatile("cp.async.wait_group 1;" ::: "memory")
#define CP_WAIT0() asm volatile("cp.async.wait_group 0;" ::: "memory")

__device__ __forceinline__ void mma8(float* d, const uint32_t* a, const uint32_t* b) {
    asm volatile(
        "mma.sync.aligned.m16n8k8.row.col.f32.tf32.tf32.f32 "
        "{%0,%1,%2,%3}, {%4,%5,%6,%7}, {%8,%9}, {%0,%1,%2,%3};"
        : "+f"(d[0]), "+f"(d[1]), "+f"(d[2]), "+f"(d[3])
        : "r"(a[0]), "r"(a[1]), "r"(a[2]), "r"(a[3]), "r"(b[0]), "r"(b[1]));
}

__device__ __forceinline__ void tf32_split(float v, float& hi, float& lo) {
    uint32_t hb, lb;
    asm("cvt.rna.tf32.f32 %0, %1;" : "=r"(hb) : "f"(v));
    float h = __uint_as_float(hb);
    float r = v - h;
    asm("cvt.rna.tf32.f32 %0, %1;" : "=r"(lb) : "f"(r));
    hi = h;
    lo = __uint_as_float(lb);
}

__global__ __launch_bounds__(256) void split_a_kernel(const float* __restrict__ a,
                                                      float* __restrict__ hi,
                                                      float* __restrict__ lo) {
    size_t i = (size_t)blockIdx.x * blockDim.x + threadIdx.x;
    float4 v = ((const float4*)a)[i];
    float4 h, l;
    tf32_split(v.x, h.x, l.x);
    tf32_split(v.y, h.y, l.y);
    tf32_split(v.z, h.z, l.z);
    tf32_split(v.w, h.w, l.w);
    ((float4*)hi)[i] = h;
    ((float4*)lo)[i] = l;
}

// W[k][n] -> hi/lo[n][k] (transposed, tf32-split)
__global__ __launch_bounds__(256) void split_w_kernel(const float* __restrict__ w,
                                                      float* __restrict__ hi,
                                                      float* __restrict__ lo) {
    __shared__ float th[32][33];
    __shared__ float tl[32][33];
    int k0 = blockIdx.y * 32, n0 = blockIdx.x * 32;
    int tx = threadIdx.x, ty = threadIdx.y;
    for (int i = ty; i < 32; i += 8) {
        float v = w[(size_t)(k0 + i) * 1024 + n0 + tx];
        tf32_split(v, th[i][tx], tl[i][tx]);
    }
    __syncthreads();
    for (int i = ty; i < 32; i += 8) {
        hi[(size_t)(n0 + i) * 1024 + k0 + tx] = th[tx][i];
        lo[(size_t)(n0 + i) * 1024 + k0 + tx] = tl[tx][i];
    }
}

// C[M,1024] = (Ah+Al)@(Bh+Bl)^T + bias, 3xTF32 mma.sync. grid=(8, M/128)
__global__ __launch_bounds__(256, 1) void mma_gemm_kernel(
    const float* __restrict__ gAh, const float* __restrict__ gAl,
    const float* __restrict__ gBh, const float* __restrict__ gBl,
    const float* __restrict__ bias, float* __restrict__ C) {
    extern __shared__ __align__(16) float sm[];
    const int tid = threadIdx.x;
    const int row0 = blockIdx.y * BM;
    const int col0 = blockIdx.x * BN;
    const int w = tid >> 5;
    const int lane = tid & 31;
    const int wm = w >> 2;          // 0..1
    const int wn = w & 3;           // 0..3
    const int g = lane >> 2;        // 0..7
    const int ctg = lane & 3;       // 0..3

    float acc[4][4][4];
#pragma unroll
    for (int mt = 0; mt < 4; mt++)
#pragma unroll
        for (int nt = 0; nt < 4; nt++)
#pragma unroll
            for (int r = 0; r < 4; r++) acc[mt][nt][r] = 0.f;

    auto load_stage = [&](int s, int kt) {
        float* dst = sm + s * STAGEF;
        const int k0 = kt * BK;
#pragma unroll
        for (int j = 0; j < 4; j++) {
            int i = j * 256 + tid;
            int r = i >> 3, c4 = i & 7;
            uint32_t da = smem_u32(dst + r * PITCH + c4 * 4);
            const size_t goff = (size_t)(row0 + r) * 1024 + k0 + c4 * 4;
            CP_ASYNC16(da, gAh + goff);
            CP_ASYNC16(da + ARR * 4, gAl + goff);
            uint32_t db = smem_u32(dst + 2 * ARR + r * PITCH + c4 * 4);
            const size_t boff = (size_t)(col0 + r) * 1024 + k0 + c4 * 4;
            CP_ASYNC16(db, gBh + boff);
            CP_ASYNC16(db + ARR * 4, gBl + boff);
        }
        CP_COMMIT();
    };

    load_stage(0, 0);

    for (int kt = 0; kt < 32; kt++) {
        if (kt + 1 < 32) {
            load_stage((kt + 1) & 1, kt + 1);
            CP_WAIT1();
        } else {
            CP_WAIT0();
        }
        __syncthreads();
        const float* st = sm + (kt & 1) * STAGEF;
        const float* sAh = st;
        const float* sAl = st + ARR;
        const float* sBh = st + 2 * ARR;
        const float* sBl = st + 3 * ARR;
#pragma unroll
        for (int ks = 0; ks < 4; ks++) {
            const int kb = ks * 8;
            uint32_t ah[4][4], al[4][4], bh[4][2], bl[4][2];
#pragma unroll
            for (int mt = 0; mt < 4; mt++) {
                int r = wm * 64 + mt * 16 + g;
                ah[mt][0] = __float_as_uint(sAh[r * PITCH + kb + ctg]);
                ah[mt][1] = __float_as_uint(sAh[(r + 8) * PITCH + kb + ctg]);
                ah[mt][2] = __float_as_uint(sAh[r * PITCH + kb + ctg + 4]);
                ah[mt][3] = __float_as_uint(sAh[(r + 8) * PITCH + kb + ctg + 4]);
                al[mt][0] = __float_as_uint(sAl[r * PITCH + kb + ctg]);
                al[mt][1] = __float_as_uint(sAl[(r + 8) * PITCH + kb + ctg]);
                al[mt][2] = __float_as_uint(sAl[r * PITCH + kb + ctg + 4]);
                al[mt][3] = __float_as_uint(sAl[(r + 8) * PITCH + kb + ctg + 4]);
            }
#pragma unroll
            for (int nt = 0; nt < 4; nt++) {
                int n = wn * 32 + nt * 8 + g;
                bh[nt][0] = __float_as_uint(sBh[n * PITCH + kb + ctg]);
                bh[nt][1] = __float_as_uint(sBh[n * PITCH + kb + ctg + 4]);
                bl[nt][0] = __float_as_uint(sBl[n * PITCH + kb + ctg]);
                bl[nt][1] = __float_as_uint(sBl[n * PITCH + kb + ctg + 4]);
            }
#pragma unroll
            for (int mt = 0; mt < 4; mt++)
#pragma unroll
                for (int nt = 0; nt < 4; nt++) mma8(acc[mt][nt], ah[mt], bh[nt]);
#pragma unroll
            for (int mt = 0; mt < 4; mt++)
#pragma unroll
                for (int nt = 0; nt < 4; nt++) mma8(acc[mt][nt], ah[mt], bl[nt]);
#pragma unroll
            for (int mt = 0; mt < 4; mt++)
#pragma unroll
                for (int nt = 0; nt < 4; nt++) mma8(acc[mt][nt], al[mt], bh[nt]);
        }
        __syncthreads();
    }

#pragma unroll
    for (int mt = 0; mt < 4; mt++) {
        int r = row0 + wm * 64 + mt * 16 + g;
#pragma unroll
        for (int nt = 0; nt < 4; nt++) {
            int c = col0 + wn * 32 + nt * 8 + ctg * 2;
            float b0 = bias[c], b1 = bias[c + 1];
            *(float2*)&C[(size_t)r * 1024 + c] =
                make_float2(acc[mt][nt][0] + b0, acc[mt][nt][1] + b1);
            *(float2*)&C[(size_t)(r + 8) * 1024 + c] =
                make_float2(acc[mt][nt][2] + b0, acc[mt][nt][3] + b1);
        }
    }
}

__global__ void mean_kernel(const float* __restrict__ q) {
    int idx = blockIdx.x * blockDim.x + threadIdx.x;
    int d = idx & (D_ - 1);
    int ba = idx / D_;
    int a = ba & (A_ - 1);
    int b = ba / A_;
    const float* base = q + ((size_t)(b * N_ + a * NA)) * D_ + d;
    float s = 0.f;
#pragma unroll 8
    for (int n = 0; n < NA; n++) s += base[(size_t)n * D_];
    g_agent_raw[idx] = s * (1.0f / NA);
}

__global__ __launch_bounds__(256) void sgemm_bias(
    const float* __restrict__ A, const float* __restrict__ W,
    const float* __restrict__ bias, float* __restrict__ C, int M) {
    __shared__ float As[16][128];
    __shared__ float Bs[16][128];
    const int t = threadIdx.x;
    const int row0 = blockIdx.y * 128;
    const int col0 = blockIdx.x * 128;
    const int tr = t >> 4;
    const int tc = t & 15;
    float acc[8][8];
#pragma unroll
    for (int i = 0; i < 8; i++)
#pragma unroll
        for (int j = 0; j < 8; j++) acc[i][j] = 0.f;
    for (int k0 = 0; k0 < 1024; k0 += 16) {
#pragma unroll
        for (int l = 0; l < 2; l++) {
            int i = t * 2 + l;
            int r = i >> 2, c4 = i & 3;
            float4 v = make_float4(0.f, 0.f, 0.f, 0.f);
            if (row0 + r < M) v = *(const float4*)&A[(size_t)(row0 + r) * 1024 + k0 + c4 * 4];
            As[c4 * 4 + 0][r] = v.x;
            As[c4 * 4 + 1][r] = v.y;
            As[c4 * 4 + 2][r] = v.z;
            As[c4 * 4 + 3][r] = v.w;
        }
#pragma unroll
        for (int l = 0; l < 2; l++) {
            int i = t * 2 + l;
            int r = i >> 5, c4 = i & 31;
            *(float4*)&Bs[r][c4 * 4] = *(const float4*)&W[(size_t)(k0 + r) * 1024 + col0 + c4 * 4];
        }
        __syncthreads();
#pragma unroll
        for (int k = 0; k < 16; k++) {
            float ra[8], rb[8];
#pragma unroll
            for (int i = 0; i < 8; i++) ra[i] = As[k][tr * 8 + i];
#pragma unroll
            for (int j = 0; j < 8; j++) rb[j] = Bs[k][tc * 8 + j];
#pragma unroll
            for (int i = 0; i < 8; i++)
#pragma unroll
                for (int j = 0; j < 8; j++) acc[i][j] += ra[i] * rb[j];
        }
        __syncthreads();
    }
    float bv[8];
#pragma unroll
    for (int j = 0; j < 8; j++) bv[j] = bias[col0 + tc * 8 + j];
#pragma unroll
    for (int i = 0; i < 8; i++) {
        int r = row0 + tr * 8 + i;
        if (r < M) {
            float4 o0 = make_float4(acc[i][0] + bv[0], acc[i][1] + bv[1],
                                    acc[i][2] + bv[2], acc[i][3] + bv[3]);
            float4 o1 = make_float4(acc[i][4] + bv[4], acc[i][5] + bv[5],
                                    acc[i][6] + bv[6], acc[i][7] + bv[7]);
            *(float4*)&C[(size_t)r * 1024 + col0 + tc * 8 + 0] = o0;
            *(float4*)&C[(size_t)r * 1024 + col0 + tc * 8 + 4] = o1;
        }
    }
}

__global__ __launch_bounds__(256) void agent_scores_kernel() {
    int bh = blockIdx.x;
    int b = bh / H_, h = bh % H_;
    int t = threadIdx.x;
    int s = blockIdx.y * 256 + t;
    __shared__ float qs[A_][DH];
    for (int i = t; i < A_ * DH; i += 256) {
        int a = i / DH, d = i % DH;
        qs[a][d] = g_qa[(b * A_ + a) * D_ + h * DH + d];
    }
    __syncthreads();
    const float4* krow = (const float4*)&g_kc[((size_t)b * S_ + s) * D_ + h * DH];
    float acc[A_];
#pragma unroll
    for (int a = 0; a < A_; a++) acc[a] = 0.f;
#pragma unroll
    for (int d4 = 0; d4 < DH / 4; d4++) {
        float4 kv = krow[d4];
#pragma unroll
        for (int a = 0; a < A_; a++) {
            acc[a] += kv.x * qs[a][d4 * 4 + 0] + kv.y * qs[a][d4 * 4 + 1] +
                      kv.z * qs[a][d4 * 4 + 2] + kv.w * qs[a][d4 * 4 + 3];
        }
    }
#pragma unroll
    for (int a = 0; a < A_; a++)
        g_attn_agent[(((size_t)bh) * A_ + a) * S_ + s] = acc[a] * SCALE_;
}

__global__ __launch_bounds__(512) void topk_softmax_kernel(float* __restrict__ w_out) {
    __shared__ float v[S_];
    __shared__ float srt[S_];
    __shared__ float red[512];
    int row = blockIdx.x;
    int t = threadIdx.x;
    const float* src = g_attn_agent + (size_t)row * S_;
    for (int i = t; i < S_; i += 512) {
        float x = src[i];
        v[i] = x;
        srt[i] = x;
    }
    __syncthreads();
    for (int k = 2; k <= S_; k <<= 1) {
        for (int j = k >> 1; j > 0; j >>= 1) {
            for (int i = t; i < S_; i += 512) {
                int ixj = i ^ j;
                if (ixj > i) {
                    bool up = ((i & k) == 0);
                    float a = srt[i], b = srt[ixj];
                    if ((a > b) == up) { srt[i] = b; srt[ixj] = a; }
                }
            }
            __syncthreads();
        }
    }
    float thresh = srt[S_ - KKEEP];
    float mx = srt[S_ - 1];
    float lsum = 0.f;
    for (int i = t; i < S_; i += 512) {
        float x = v[i];
        float e = (x >= thresh) ? expf(x - mx) : 0.f;
        v[i] = e;
        lsum += e;
    }
    red[t] = lsum;
    __syncthreads();
    for (int o = 256; o > 0; o >>= 1) {
        if (t < o) red[t] += red[t + o];
        __syncthreads();
    }
    float inv = 1.f / red[0];
    float* dst = w_out + (size_t)row * S_;
    for (int i = t; i < S_; i += 512) dst[i] = v[i] * inv;
}

__global__ __launch_bounds__(512) void agent_out_kernel(const float* __restrict__ w) {
    int bh = blockIdx.x;
    int b = bh / H_, h = bh % H_;
    int t = threadIdx.x;
    int a = t / DH, d = t % DH;
    __shared__ float ws[A_][256];
    const float* wbase = w + ((size_t)bh * A_) * S_;
    const float* vbase = g_vc + ((size_t)b * S_) * D_ + h * DH;
    float acc = 0.f;
    for (int s0 = 0; s0 < S_; s0 += 256) {
        for (int i = t; i < A_ * 256; i += 512) {
            int aa = i >> 8, ss = i & 255;
            ws[aa][ss] = wbase[(size_t)aa * S_ + s0 + ss];
        }
        __syncthreads();
#pragma unroll 8
        for (int ss = 0; ss < 256; ss++)
            acc += ws[a][ss] * vbase[(size_t)(s0 + ss) * D_ + d];
        __syncthreads();
    }
    g_agent_out[(b * A_ + a) * D_ + h * DH + d] = acc;
}

__global__ __launch_bounds__(256) void final_attn_kernel(float* __restrict__ attn_out) {
    int bh = blockIdx.x;
    int b = bh / H_, h = bh % H_;
    int t = threadIdx.x;
    int n = blockIdx.y * 256 + t;
    __shared__ float ks[A_][DH], vs[A_][DH];
    for (int i = t; i < A_ * DH; i += 256) {
        int a = i / DH, d = i % DH;
        ks[a][d] = g_ka[(b * A_ + a) * D_ + h * DH + d];
        vs[a][d] = g_va[(b * A_ + a) * D_ + h * DH + d];
    }
    __syncthreads();
    const float4* qrow = (const float4*)&g_qo[((size_t)b * N_ + n) * D_ + h * DH];
    float sc[A_];
#pragma unroll
    for (int a = 0; a < A_; a++) sc[a] = 0.f;
#pragma unroll
    for (int d4 = 0; d4 < DH / 4; d4++) {
        float4 q = qrow[d4];
#pragma unroll
        for (int a = 0; a < A_; a++) {
            sc[a] += q.x * ks[a][d4 * 4 + 0] + q.y * ks[a][d4 * 4 + 1] +
                     q.z * ks[a][d4 * 4 + 2] + q.w * ks[a][d4 * 4 + 3];
        }
    }
    float mx = -1e30f;
#pragma unroll
    for (int a = 0; a < A_; a++) {
        sc[a] *= SCALE_;
        mx = fmaxf(mx, sc[a]);
    }
    float sum = 0.f;
#pragma unroll
    for (int a = 0; a < A_; a++) {
        sc[a] = expf(sc[a] - mx);
        sum += sc[a];
    }
    float inv = 1.f / sum;
#pragma unroll
    for (int a = 0; a < A_; a++) sc[a] *= inv;
    float* ao = attn_out + (((size_t)bh) * N_ + n) * A_;
#pragma unroll
    for (int a = 0; a < A_; a++) ao[a] = sc[a];
    float4* orow = (float4*)&g_outpre[((size_t)b * N_ + n) * D_ + h * DH];
#pragma unroll
    for (int d4 = 0; d4 < DH / 4; d4++) {
        float4 o = make_float4(0.f, 0.f, 0.f, 0.f);
#pragma unroll
        for (int a = 0; a < A_; a++) {
            float w = sc[a];
            o.x += w * vs[a][d4 * 4 + 0];
            o.y += w * vs[a][d4 * 4 + 1];
            o.z += w * vs[a][d4 * 4 + 2];
            o.w += w * vs[a][d4 * 4 + 3];
        }
        orow[d4] = o;
    }
}

extern "C" void kernel_launch(void* const* d_in, const int* in_sizes, int n_in,
                              void* d_out, int out_size) {
    const float* query = (const float*)d_in[0];
    const float* key = (const float*)d_in[1];
    const float* value = (const float*)d_in[2];
    const float* W_agent = (const float*)d_in[3];
    const float* b_agent = (const float*)d_in[4];
    const float* W_qa = (const float*)d_in[5];
    const float* b_qa = (const float*)d_in[6];
    const float* W_kc = (const float*)d_in[7];
    const float* b_kc = (const float*)d_in[8];
    const float* W_vc = (const float*)d_in[9];
    const float* b_vc = (const float*)d_in[10];
    const float* W_qo = (const float*)d_in[11];
    const float* b_qo = (const float*)d_in[12];
    const float* W_ka = (const float*)d_in[13];
    const float* b_ka = (const float*)d_in[14];
    const float* W_va = (const float*)d_in[15];
    const float* b_va = (const float*)d_in[16];
    const float* W_proj = (const float*)d_in[17];
    const float* b_proj = (const float*)d_in[18];

    float* out0 = (float*)d_out;
    float* out_attn_final = out0 + (size_t)B_ * N_ * D_;
    float* out_attn_agent_w = out_attn_final + (size_t)B_ * H_ * N_ * A_;

    float *p_raw, *p_tok, *p_qa, *p_kc, *p_vc, *p_qo, *p_ka, *p_va, *p_aout, *p_outpre;
    float *p_ah, *p_al, *p_bh, *p_bl;
    cudaGetSymbolAddress((void**)&p_raw, g_agent_raw);
    cudaGetSymbolAddress((void**)&p_tok, g_agent_tok);
    cudaGetSymbolAddress((void**)&p_qa, g_qa);
    cudaGetSymbolAddress((void**)&p_kc, g_kc);
    cudaGetSymbolAddress((void**)&p_vc, g_vc);
    cudaGetSymbolAddress((void**)&p_qo, g_qo);
    cudaGetSymbolAddress((void**)&p_ka, g_ka);
    cudaGetSymbolAddress((void**)&p_va, g_va);
    cudaGetSymbolAddress((void**)&p_aout, g_agent_out);
    cudaGetSymbolAddress((void**)&p_outpre, g_outpre);
    cudaGetSymbolAddress((void**)&p_ah, g_ah);
    cudaGetSymbolAddress((void**)&p_al, g_al);
    cudaGetSymbolAddress((void**)&p_bh, g_bh);
    cudaGetSymbolAddress((void**)&p_bl, g_bl);

    cudaFuncSetAttribute(mma_gemm_kernel,
                         cudaFuncAttributeMaxDynamicSharedMemorySize, SMEM_MMA);

    const int MBIG = B_ * N_;   // 32768
    const int MSM = B_ * A_;    // 64
    dim3 gsm(8, 1);
    dim3 gbig(8, MBIG / 128);                 // fp32 sgemm grid (k_c)
    dim3 gmma(1024 / BN, MBIG / BM);          // (8, 256)
    dim3 gsw(32, 32);
    dim3 bsw(32, 8);
    const int SA_BLK = (MBIG * D_ / 4) / 256;

    mean_kernel<<<(B_ * A_ * D_) / 256, 256>>>(query);
    sgemm_bias<<<gsm, 256>>>(p_raw, W_agent, b_agent, p_tok, MSM);
    sgemm_bias<<<gsm, 256>>>(p_tok, W_qa, b_qa, p_qa, MSM);

    // k_c in exact fp32 (determines top-k flips -> must match R1 baseline bit-for-bit)
    sgemm_bias<<<gbig, 256>>>(key, W_kc, b_kc, p_kc, MBIG);

    // v_c, q_o in 3xTF32 tensor-core GEMM (smooth paths)
    split_a_kernel<<<SA_BLK, 256>>>(value, p_ah, p_al);
    split_w_kernel<<<gsw, bsw>>>(W_vc, p_bh, p_bl);
    mma_gemm_kernel<<<gmma, 256, SMEM_MMA>>>(p_ah, p_al, p_bh, p_bl, b_vc, p_vc);

    split_a_kernel<<<SA_BLK, 256>>>(query, p_ah, p_al);
    split_w_kernel<<<gsw, bsw>>>(W_qo, p_bh, p_bl);
    mma_gemm_kernel<<<gmma, 256, SMEM_MMA>>>(p_ah, p_al, p_bh, p_bl, b_qo, p_qo);

    agent_scores_kernel<<<dim3(B_ * H_, S_ / 256), 256>>>();
    topk_softmax_kernel<<<B_ * H_ * A_, 512>>>(out_attn_agent_w);
    agent_out_kernel<<<B_ * H_, 512>>>(out_attn_agent_w);
    sgemm_bias<<<gsm, 256>>>(p_aout, W_ka, b_ka, p_ka, MSM);
    sgemm_bias<<<gsm, 256>>>(p_aout, W_va, b_va, p_va, MSM);
    final_attn_kernel<<<dim3(B_ * H_, N_ / 256), 256>>>(out_attn_final);

    split_a_kernel<<<SA_BLK, 256>>>(p_outpre, p_ah, p_al);
    split_w_kernel<<<gsw, bsw>>>(W_proj, p_bh, p_bl);
    mma_gemm_kernel<<<gmma, 256, SMEM_MMA>>>(p_ah, p_al, p_bh, p_bl, b_proj, out0);
}

// round 7
// speedup vs baseline: 1.2200x; 1.0213x over previous
#include <cuda_runtime.h>
#include <cstddef>
#include <cstdint>

#define B_ 8
#define N_ 4096
#define S_ 4096
#define D_ 1024
#define H_ 16
#define A_ 8
#define DH 64
#define NA 512
#define KKEEP 2048
#define SCALE_ 0.125f

// mma tiling
#define BM 128
#define BN 128
#define BK 32
#define PITCH 36
#define ARR (128 * PITCH)
#define STAGEF (4 * ARR)
#define SMEM_MMA (2 * STAGEF * 4)

__device__ float g_kc[(size_t)B_ * S_ * D_];
__device__ float g_vc[(size_t)B_ * S_ * D_];
__device__ float g_qo[(size_t)B_ * N_ * D_];
__device__ float g_attn_agent[(size_t)B_ * H_ * A_ * S_];
__device__ float g_agent_raw[B_ * A_ * D_];
__device__ float g_agent_tok[B_ * A_ * D_];
__device__ float g_qa[B_ * A_ * D_];
__device__ float g_ka[B_ * A_ * D_];
__device__ float g_va[B_ * A_ * D_];
__device__ float g_agent_out[B_ * A_ * D_];
// tf32 split scratch: g_ah/g_al used for value (s1), then reused for outpre split
__device__ float g_ah[(size_t)B_ * N_ * D_];
__device__ float g_al[(size_t)B_ * N_ * D_];
__device__ float g_ah2[(size_t)B_ * N_ * D_];   // query split (s2)
__device__ float g_al2[(size_t)B_ * N_ * D_];
__device__ float g_bh1[(size_t)D_ * D_], g_bl1[(size_t)D_ * D_];   // W_vc
__device__ float g_bh2[(size_t)D_ * D_], g_bl2[(size_t)D_ * D_];   // W_qo
__device__ float g_bh3[(size_t)D_ * D_], g_bl3[(size_t)D_ * D_];   // W_proj

__device__ __forceinline__ uint32_t smem_u32(const void* p) {
    uint32_t a;
    asm("{ .reg .u64 t; cvta.to.shared.u64 t, %1; cvt.u32.u64 %0, t; }" : "=r"(a) : "l"(p));
    return a;
}
#define CP_ASYNC16(dst, src) \
    asm volatile("cp.async.cg.shared.global [%0], [%1], 16;" :: "r"(dst), "l"(src) : "memory")
#define CP_COMMIT() asm volatile("cp.async.commit_group;" ::: "memory")
#define CP_WAIT1() asm volatile("cp.async.wait_group 1;" ::: "memory")
#define CP_WAIT0() asm volatile("cp.async.wait_group 0;" ::: "memory")

__device__ __forceinline__ void mma8(float* d, const uint32_t* a, const uint32_t* b) {
    asm volatile(
        "mma.sync.aligned.m16n8k8.row.col.f32.tf32.tf32.f32 "
        "{%0,%1,%2,%3}, {%4,%5,%6,%7}, {%8,%9}, {%0,%1,%2,%3};"
        : "+f"(d[0]), "+f"(d[1]), "+f"(d[2]), "+f"(d[3])
        : "r"(a[0]), "r"(a[1]), "r"(a[2]), "r"(a[3]), "r"(b[0]), "r"(b[1]));
}

__device__ __forceinline__ void tf32_split(float v, float& hi, float& lo) {
    uint32_t hb, lb;
    asm("cvt.rna.tf32.f32 %0, %1;" : "=r"(hb) : "f"(v));
    float h = __uint_as_float(hb);
    float r = v - h;
    asm("cvt.rna.tf32.f32 %0, %1;" : "=r"(lb) : "f"(r));
    hi = h;
    lo = __uint_as_float(lb);
}

__global__ __launch_bounds__(256) void split_a_kernel(const float* __restrict__ a,
                                                      float* __restrict__ hi,
                                                      float* __restrict__ lo) {
    size_t i = (size_t)blockIdx.x * blockDim.x + threadIdx.x;
    float4 v = ((const float4*)a)[i];
    float4 h, l;
    tf32_split(v.x, h.x, l.x);
    tf32_split(v.y, h.y, l.y);
    tf32_split(v.z, h.z, l.z);
    tf32_split(v.w, h.w, l.w);
    ((float4*)hi)[i] = h;
    ((float4*)lo)[i] = l;
}

// W[k][n] -> hi/lo[n][k] (transposed, tf32-split)
__global__ __launch_bounds__(256) void split_w_kernel(const float* __restrict__ w,
                                                      float* __restrict__ hi,
                                                      float* __restrict__ lo) {
    __shared__ float th[32][33];
    __shared__ float tl[32][33];
    int k0 = blockIdx.y * 32, n0 = blockIdx.x * 32;
    int tx = threadIdx.x, ty = threadIdx.y;
    for (int i = ty; i < 32; i += 8) {
        float v = w[(size_t)(k0 + i) * 1024 + n0 + tx];
        tf32_split(v, th[i][tx], tl[i][tx]);
    }
    __syncthreads();
    for (int i = ty; i < 32; i += 8) {
        hi[(size_t)(n0 + i) * 1024 + k0 + tx] = th[tx][i];
        lo[(size_t)(n0 + i) * 1024 + k0 + tx] = tl[tx][i];
    }
}

// C[M,1024] = (Ah+Al)@(Bh+Bl)^T + bias, 3xTF32 mma.sync. grid=(8, M/128)
__global__ __launch_bounds__(256, 1) void mma_gemm_kernel(
    const float* __restrict__ gAh, const float* __restrict__ gAl,
    const float* __restrict__ gBh, const float* __restrict__ gBl,
    const float* __restrict__ bias, float* __restrict__ C) {
    extern __shared__ __align__(16) float sm[];
    const int tid = threadIdx.x;
    const int row0 = blockIdx.y * BM;
    const int col0 = blockIdx.x * BN;
    const int w = tid >> 5;
    const int lane = tid & 31;
    const int wm = w >> 2;
    const int wn = w & 3;
    const int g = lane >> 2;
    const int ctg = lane & 3;

    float acc[4][4][4];
#pragma unroll
    for (int mt = 0; mt < 4; mt++)
#pragma unroll
        for (int nt = 0; nt < 4; nt++)
#pragma unroll
            for (int r = 0; r < 4; r++) acc[mt][nt][r] = 0.f;

    auto load_stage = [&](int s, int kt) {
        float* dst = sm + s * STAGEF;
        const int k0 = kt * BK;
#pragma unroll
        for (int j = 0; j < 4; j++) {
            int i = j * 256 + tid;
            int r = i >> 3, c4 = i & 7;
            uint32_t da = smem_u32(dst + r * PITCH + c4 * 4);
            const size_t goff = (size_t)(row0 + r) * 1024 + k0 + c4 * 4;
            CP_ASYNC16(da, gAh + goff);
            CP_ASYNC16(da + ARR * 4, gAl + goff);
            uint32_t db = smem_u32(dst + 2 * ARR + r * PITCH + c4 * 4);
            const size_t boff = (size_t)(col0 + r) * 1024 + k0 + c4 * 4;
            CP_ASYNC16(db, gBh + boff);
            CP_ASYNC16(db + ARR * 4, gBl + boff);
        }
        CP_COMMIT();
    };

    load_stage(0, 0);

    for (int kt = 0; kt < 32; kt++) {
        if (kt + 1 < 32) {
            load_stage((kt + 1) & 1, kt + 1);
            CP_WAIT1();
        } else {
            CP_WAIT0();
        }
        __syncthreads();
        const float* st = sm + (kt & 1) * STAGEF;
        const float* sAh = st;
        const float* sAl = st + ARR;
        const float* sBh = st + 2 * ARR;
        const float* sBl = st + 3 * ARR;
#pragma unroll
        for (int ks = 0; ks < 4; ks++) {
            const int kb = ks * 8;
            uint32_t ah[4][4], al[4][4], bh[4][2], bl[4][2];
#pragma unroll
            for (int mt = 0; mt < 4; mt++) {
                int r = wm * 64 + mt * 16 + g;
                ah[mt][0] = __float_as_uint(sAh[r * PITCH + kb + ctg]);
                ah[mt][1] = __float_as_uint(sAh[(r + 8) * PITCH + kb + ctg]);
                ah[mt][2] = __float_as_uint(sAh[r * PITCH + kb + ctg + 4]);
                ah[mt][3] = __float_as_uint(sAh[(r + 8) * PITCH + kb + ctg + 4]);
                al[mt][0] = __float_as_uint(sAl[r * PITCH + kb + ctg]);
                al[mt][1] = __float_as_uint(sAl[(r + 8) * PITCH + kb + ctg]);
                al[mt][2] = __float_as_uint(sAl[r * PITCH + kb + ctg + 4]);
                al[mt][3] = __float_as_uint(sAl[(r + 8) * PITCH + kb + ctg + 4]);
            }
#pragma unroll
            for (int nt = 0; nt < 4; nt++) {
                int n = wn * 32 + nt * 8 + g;
                bh[nt][0] = __float_as_uint(sBh[n * PITCH + kb + ctg]);
                bh[nt][1] = __float_as_uint(sBh[n * PITCH + kb + ctg + 4]);
                bl[nt][0] = __float_as_uint(sBl[n * PITCH + kb + ctg]);
                bl[nt][1] = __float_as_uint(sBl[n * PITCH + kb + ctg + 4]);
            }
#pragma unroll
            for (int mt = 0; mt < 4; mt++)
#pragma unroll
                for (int nt = 0; nt < 4; nt++) mma8(acc[mt][nt], ah[mt], bh[nt]);
#pragma unroll
            for (int mt = 0; mt < 4; mt++)
#pragma unroll
                for (int nt = 0; nt < 4; nt++) mma8(acc[mt][nt], ah[mt], bl[nt]);
#pragma unroll
            for (int mt = 0; mt < 4; mt++)
#pragma unroll
                for (int nt = 0; nt < 4; nt++) mma8(acc[mt][nt], al[mt], bh[nt]);
        }
        __syncthreads();
    }

#pragma unroll
    for (int mt = 0; mt < 4; mt++) {
        int r = row0 + wm * 64 + mt * 16 + g;
#pragma unroll
        for (int nt = 0; nt < 4; nt++) {
            int c = col0 + wn * 32 + nt * 8 + ctg * 2;
            float b0 = bias[c], b1 = bias[c + 1];
            *(float2*)&C[(size_t)r * 1024 + c] =
                make_float2(acc[mt][nt][0] + b0, acc[mt][nt][1] + b1);
            *(float2*)&C[(size_t)(r + 8) * 1024 + c] =
                make_float2(acc[mt][nt][2] + b0, acc[mt][nt][3] + b1);
        }
    }
}

__global__ void mean_kernel(const float* __restrict__ q) {
    int idx = blockIdx.x * blockDim.x + threadIdx.x;
    int d = idx & (D_ - 1);
    int ba = idx / D_;
    int a = ba & (A_ - 1);
    int b = ba / A_;
    const float* base = q + ((size_t)(b * N_ + a * NA)) * D_ + d;
    float s = 0.f;
#pragma unroll 8
    for (int n = 0; n < NA; n++) s += base[(size_t)n * D_];
    g_agent_raw[idx] = s * (1.0f / NA);
}

__global__ __launch_bounds__(256) void sgemm_bias(
    const float* __restrict__ A, const float* __restrict__ W,
    const float* __restrict__ bias, float* __restrict__ C, int M) {
    __shared__ float As[16][128];
    __shared__ float Bs[16][128];
    const int t = threadIdx.x;
    const int row0 = blockIdx.y * 128;
    const int col0 = blockIdx.x * 128;
    const int tr = t >> 4;
    const int tc = t & 15;
    float acc[8][8];
#pragma unroll
    for (int i = 0; i < 8; i++)
#pragma unroll
        for (int j = 0; j < 8; j++) acc[i][j] = 0.f;
    for (int k0 = 0; k0 < 1024; k0 += 16) {
#pragma unroll
        for (int l = 0; l < 2; l++) {
            int i = t * 2 + l;
            int r = i >> 2, c4 = i & 3;
            float4 v = make_float4(0.f, 0.f, 0.f, 0.f);
            if (row0 + r < M) v = *(const float4*)&A[(size_t)(row0 + r) * 1024 + k0 + c4 * 4];
            As[c4 * 4 + 0][r] = v.x;
            As[c4 * 4 + 1][r] = v.y;
            As[c4 * 4 + 2][r] = v.z;
            As[c4 * 4 + 3][r] = v.w;
        }
#pragma unroll
        for (int l = 0; l < 2; l++) {
            int i = t * 2 + l;
            int r = i >> 5, c4 = i & 31;
            *(float4*)&Bs[r][c4 * 4] = *(const float4*)&W[(size_t)(k0 + r) * 1024 + col0 + c4 * 4];
        }
        __syncthreads();
#pragma unroll
        for (int k = 0; k < 16; k++) {
            float ra[8], rb[8];
#pragma unroll
            for (int i = 0; i < 8; i++) ra[i] = As[k][tr * 8 + i];
#pragma unroll
            for (int j = 0; j < 8; j++) rb[j] = Bs[k][tc * 8 + j];
#pragma unroll
            for (int i = 0; i < 8; i++)
#pragma unroll
                for (int j = 0; j < 8; j++) acc[i][j] += ra[i] * rb[j];
        }
        __syncthreads();
    }
    float bv[8];
#pragma unroll
    for (int j = 0; j < 8; j++) bv[j] = bias[col0 + tc * 8 + j];
#pragma unroll
    for (int i = 0; i < 8; i++) {
        int r = row0 + tr * 8 + i;
        if (r < M) {
            float4 o0 = make_float4(acc[i][0] + bv[0], acc[i][1] + bv[1],
                                    acc[i][2] + bv[2], acc[i][3] + bv[3]);
            float4 o1 = make_float4(acc[i][4] + bv[4], acc[i][5] + bv[5],
                                    acc[i][6] + bv[6], acc[i][7] + bv[7]);
            *(float4*)&C[(size_t)r * 1024 + col0 + tc * 8 + 0] = o0;
            *(float4*)&C[(size_t)r * 1024 + col0 + tc * 8 + 4] = o1;
        }
    }
}

__global__ __launch_bounds__(256) void agent_scores_kernel() {
    int bh = blockIdx.x;
    int b = bh / H_, h = bh % H_;
    int t = threadIdx.x;
    int s = blockIdx.y * 256 + t;
    __shared__ float qs[A_][DH];
    for (int i = t; i < A_ * DH; i += 256) {
        int a = i / DH, d = i % DH;
        qs[a][d] = g_qa[(b * A_ + a) * D_ + h * DH + d];
    }
    __syncthreads();
    const float4* krow = (const float4*)&g_kc[((size_t)b * S_ + s) * D_ + h * DH];
    float acc[A_];
#pragma unroll
    for (int a = 0; a < A_; a++) acc[a] = 0.f;
#pragma unroll
    for (int d4 = 0; d4 < DH / 4; d4++) {
        float4 kv = krow[d4];
#pragma unroll
        for (int a = 0; a < A_; a++) {
            acc[a] += kv.x * qs[a][d4 * 4 + 0] + kv.y * qs[a][d4 * 4 + 1] +
                      kv.z * qs[a][d4 * 4 + 2] + kv.w * qs[a][d4 * 4 + 3];
        }
    }
#pragma unroll
    for (int a = 0; a < A_; a++)
        g_attn_agent[(((size_t)bh) * A_ + a) * S_ + s] = acc[a] * SCALE_;
}

__global__ __launch_bounds__(512) void topk_softmax_kernel(float* __restrict__ w_out) {
    __shared__ float v[S_];
    __shared__ float srt[S_];
    __shared__ float red[512];
    int row = blockIdx.x;
    int t = threadIdx.x;
    const float* src = g_attn_agent + (size_t)row * S_;
    for (int i = t; i < S_; i += 512) {
        float x = src[i];
        v[i] = x;
        srt[i] = x;
    }
    __syncthreads();
    for (int k = 2; k <= S_; k <<= 1) {
        for (int j = k >> 1; j > 0; j >>= 1) {
            for (int i = t; i < S_; i += 512) {
                int ixj = i ^ j;
                if (ixj > i) {
                    bool up = ((i & k) == 0);
                    float a = srt[i], b = srt[ixj];
                    if ((a > b) == up) { srt[i] = b; srt[ixj] = a; }
                }
            }
            __syncthreads();
        }
    }
    float thresh = srt[S_ - KKEEP];
    float mx = srt[S_ - 1];
    float lsum = 0.f;
    for (int i = t; i < S_; i += 512) {
        float x = v[i];
        float e = (x >= thresh) ? expf(x - mx) : 0.f;
        v[i] = e;
        lsum += e;
    }
    red[t] = lsum;
    __syncthreads();
    for (int o = 256; o > 0; o >>= 1) {
        if (t < o) red[t] += red[t + o];
        __syncthreads();
    }
    float inv = 1.f / red[0];
    float* dst = w_out + (size_t)row * S_;
    for (int i = t; i < S_; i += 512) dst[i] = v[i] * inv;
}

__global__ __launch_bounds__(512) void agent_out_kernel(const float* __restrict__ w) {
    int bh = blockIdx.x;
    int b = bh / H_, h = bh % H_;
    int t = threadIdx.x;
    int a = t / DH, d = t % DH;
    __shared__ float ws[A_][256];
    const float* wbase = w + ((size_t)bh * A_) * S_;
    const float* vbase = g_vc + ((size_t)b * S_) * D_ + h * DH;
    float acc = 0.f;
    for (int s0 = 0; s0 < S_; s0 += 256) {
        for (int i = t; i < A_ * 256; i += 512) {
            int aa = i >> 8, ss = i & 255;
            ws[aa][ss] = wbase[(size_t)aa * S_ + s0 + ss];
        }
        __syncthreads();
#pragma unroll 8
        for (int ss = 0; ss < 256; ss++)
            acc += ws[a][ss] * vbase[(size_t)(s0 + ss) * D_ + d];
        __syncthreads();
    }
    g_agent_out[(b * A_ + a) * D_ + h * DH + d] = acc;
}

// writes attn_final AND the tf32-split of outpre directly into g_ah/g_al
__global__ __launch_bounds__(256) void final_attn_kernel(float* __restrict__ attn_out) {
    int bh = blockIdx.x;
    int b = bh / H_, h = bh % H_;
    int t = threadIdx.x;
    int n = blockIdx.y * 256 + t;
    __shared__ float ks[A_][DH], vs[A_][DH];
    for (int i = t; i < A_ * DH; i += 256) {
        int a = i / DH, d = i % DH;
        ks[a][d] = g_ka[(b * A_ + a) * D_ + h * DH + d];
        vs[a][d] = g_va[(b * A_ + a) * D_ + h * DH + d];
    }
    __syncthreads();
    const float4* qrow = (const float4*)&g_qo[((size_t)b * N_ + n) * D_ + h * DH];
    float sc[A_];
#pragma unroll
    for (int a = 0; a < A_; a++) sc[a] = 0.f;
#pragma unroll
    for (int d4 = 0; d4 < DH / 4; d4++) {
        float4 q = qrow[d4];
#pragma unroll
        for (int a = 0; a < A_; a++) {
            sc[a] += q.x * ks[a][d4 * 4 + 0] + q.y * ks[a][d4 * 4 + 1] +
                     q.z * ks[a][d4 * 4 + 2] + q.w * ks[a][d4 * 4 + 3];
        }
    }
    float mx = -1e30f;
#pragma unroll
    for (int a = 0; a < A_; a++) {
        sc[a] *= SCALE_;
        mx = fmaxf(mx, sc[a]);
    }
    float sum = 0.f;
#pragma unroll
    for (int a = 0; a < A_; a++) {
        sc[a] = expf(sc[a] - mx);
        sum += sc[a];
    }
    float inv = 1.f / sum;
#pragma unroll
    for (int a = 0; a < A_; a++) sc[a] *= inv;
    float* ao = attn_out + (((size_t)bh) * N_ + n) * A_;
#pragma unroll
    for (int a = 0; a < A_; a++) ao[a] = sc[a];
    const size_t obase = ((size_t)b * N_ + n) * D_ + h * DH;
    float4* ohp = (float4*)&g_ah[obase];
    float4* olp = (float4*)&g_al[obase];
#pragma unroll
    for (int d4 = 0; d4 < DH / 4; d4++) {
        float4 o = make_float4(0.f, 0.f, 0.f, 0.f);
#pragma unroll
        for (int a = 0; a < A_; a++) {
            float w = sc[a];
            o.x += w * vs[a][d4 * 4 + 0];
            o.y += w * vs[a][d4 * 4 + 1];
            o.z += w * vs[a][d4 * 4 + 2];
            o.w += w * vs[a][d4 * 4 + 3];
        }
        float4 hh, ll;
        tf32_split(o.x, hh.x, ll.x);
        tf32_split(o.y, hh.y, ll.y);
        tf32_split(o.z, hh.z, ll.z);
        tf32_split(o.w, hh.w, ll.w);
        ohp[d4] = hh;
        olp[d4] = ll;
    }
}

extern "C" void kernel_launch(void* const* d_in, const int* in_sizes, int n_in,
                              void* d_out, int out_size) {
    const float* query = (const float*)d_in[0];
    const float* key = (const float*)d_in[1];
    const float* value = (const float*)d_in[2];
    const float* W_agent = (const float*)d_in[3];
    const float* b_agent = (const float*)d_in[4];
    const float* W_qa = (const float*)d_in[5];
    const float* b_qa = (const float*)d_in[6];
    const float* W_kc = (const float*)d_in[7];
    const float* b_kc = (const float*)d_in[8];
    const float* W_vc = (const float*)d_in[9];
    const float* b_vc = (const float*)d_in[10];
    const float* W_qo = (const float*)d_in[11];
    const float* b_qo = (const float*)d_in[12];
    const float* W_ka = (const float*)d_in[13];
    const float* b_ka = (const float*)d_in[14];
    const float* W_va = (const float*)d_in[15];
    const float* b_va = (const float*)d_in[16];
    const float* W_proj = (const float*)d_in[17];
    const float* b_proj = (const float*)d_in[18];

    float* out0 = (float*)d_out;
    float* out_attn_final = out0 + (size_t)B_ * N_ * D_;
    float* out_attn_agent_w = out_attn_final + (size_t)B_ * H_ * N_ * A_;

    float *p_raw, *p_tok, *p_qa, *p_kc, *p_vc, *p_qo, *p_ka, *p_va, *p_aout;
    float *p_ah, *p_al, *p_ah2, *p_al2, *p_bh1, *p_bl1, *p_bh2, *p_bl2, *p_bh3, *p_bl3;
    cudaGetSymbolAddress((void**)&p_raw, g_agent_raw);
    cudaGetSymbolAddress((void**)&p_tok, g_agent_tok);
    cudaGetSymbolAddress((void**)&p_qa, g_qa);
    cudaGetSymbolAddress((void**)&p_kc, g_kc);
    cudaGetSymbolAddress((void**)&p_vc, g_vc);
    cudaGetSymbolAddress((void**)&p_qo, g_qo);
    cudaGetSymbolAddress((void**)&p_ka, g_ka);
    cudaGetSymbolAddress((void**)&p_va, g_va);
    cudaGetSymbolAddress((void**)&p_aout, g_agent_out);
    cudaGetSymbolAddress((void**)&p_ah, g_ah);
    cudaGetSymbolAddress((void**)&p_al, g_al);
    cudaGetSymbolAddress((void**)&p_ah2, g_ah2);
    cudaGetSymbolAddress((void**)&p_al2, g_al2);
    cudaGetSymbolAddress((void**)&p_bh1, g_bh1);
    cudaGetSymbolAddress((void**)&p_bl1, g_bl1);
    cudaGetSymbolAddress((void**)&p_bh2, g_bh2);
    cudaGetSymbolAddress((void**)&p_bl2, g_bl2);
    cudaGetSymbolAddress((void**)&p_bh3, g_bh3);
    cudaGetSymbolAddress((void**)&p_bl3, g_bl3);

    static cudaStream_t s1 = nullptr, s2 = nullptr;
    static cudaEvent_t evRoot = nullptr, evVC = nullptr, evQO = nullptr;
    if (!s1) {
        cudaStreamCreateWithFlags(&s1, cudaStreamNonBlocking);
        cudaStreamCreateWithFlags(&s2, cudaStreamNonBlocking);
        cudaEventCreateWithFlags(&evRoot, cudaEventDisableTiming);
        cudaEventCreateWithFlags(&evVC, cudaEventDisableTiming);
        cudaEventCreateWithFlags(&evQO, cudaEventDisableTiming);
        cudaFuncSetAttribute(mma_gemm_kernel,
                             cudaFuncAttributeMaxDynamicSharedMemorySize, SMEM_MMA);
    }

    const int MBIG = B_ * N_;   // 32768
    const int MSM = B_ * A_;    // 64
    dim3 gsm(8, 1);
    dim3 gbig(8, MBIG / 128);
    dim3 gmma(1024 / BN, MBIG / BM);
    dim3 gsw(32, 32);
    dim3 bsw(32, 8);
    const int SA_BLK = (MBIG * D_ / 4) / 256;

    // ---- fork side streams ----
    cudaEventRecord(evRoot, 0);
    cudaStreamWaitEvent(s1, evRoot, 0);
    cudaStreamWaitEvent(s2, evRoot, 0);

    // s1: v_c pipeline
    split_w_kernel<<<gsw, bsw, 0, s1>>>(W_vc, p_bh1, p_bl1);
    split_a_kernel<<<SA_BLK, 256, 0, s1>>>(value, p_ah, p_al);
    mma_gemm_kernel<<<gmma, 256, SMEM_MMA, s1>>>(p_ah, p_al, p_bh1, p_bl1, b_vc, p_vc);
    cudaEventRecord(evVC, s1);

    // s2: q_o pipeline + proj weight split
    split_w_kernel<<<gsw, bsw, 0, s2>>>(W_qo, p_bh2, p_bl2);
    split_a_kernel<<<SA_BLK, 256, 0, s2>>>(query, p_ah2, p_al2);
    mma_gemm_kernel<<<gmma, 256, SMEM_MMA, s2>>>(p_ah2, p_al2, p_bh2, p_bl2, b_qo, p_qo);
    split_w_kernel<<<gsw, bsw, 0, s2>>>(W_proj, p_bh3, p_bl3);
    cudaEventRecord(evQO, s2);

    // s0: flip-determining path (unchanged numerics)
    mean_kernel<<<(B_ * A_ * D_) / 256, 256>>>(query);
    sgemm_bias<<<gsm, 256>>>(p_raw, W_agent, b_agent, p_tok, MSM);
    sgemm_bias<<<gsm, 256>>>(p_tok, W_qa, b_qa, p_qa, MSM);
    sgemm_bias<<<gbig, 256>>>(key, W_kc, b_kc, p_kc, MBIG);
    agent_scores_kernel<<<dim3(B_ * H_, S_ / 256), 256>>>();
    topk_softmax_kernel<<<B_ * H_ * A_, 512>>>(out_attn_agent_w);

    cudaStreamWaitEvent(0, evVC, 0);      // join s1 (need v_c)
    agent_out_kernel<<<B_ * H_, 512>>>(out_attn_agent_w);
    sgemm_bias<<<gsm, 256>>>(p_aout, W_ka, b_ka, p_ka, MSM);
    sgemm_bias<<<gsm, 256>>>(p_aout, W_va, b_va, p_va, MSM);

    cudaStreamWaitEvent(0, evQO, 0);      // join s2 (need q_o + proj weights)
    final_attn_kernel<<<dim3(B_ * H_, N_ / 256), 256>>>(out_attn_final);
    mma_gemm_kernel<<<gmma, 256, SMEM_MMA>>>(p_ah, p_al, p_bh3, p_bl3, b_proj, out0);
}